// round 1
// baseline (speedup 1.0000x reference)
#include <cuda_runtime.h>
#include <cuda_bf16.h>

#define NN   50000
#define NE   800000
#define NB   4
#define IND  64
#define HIDD 64
#define OUTD 32

// ---------------- scratch (static device globals; no allocation) ----------------
__device__ float g_z1  [(size_t)NN * NB * HIDD];   // (h @ W1) * s_norm,  node-major [N, B*64]
__device__ float g_agg1[(size_t)NN * NB * HIDD];   // scatter target layer 1
__device__ float g_z2  [(size_t)NN * NB * OUTD];   // (relu(...) @ W2) * s_norm, [N, B*32]
__device__ float g_agg2[(size_t)NN * NB * OUTD];   // scatter target layer 2
__device__ float g_snorm[NN];
__device__ float g_dnorm[NN];
__device__ int   g_odeg[NN];
__device__ int   g_ideg[NN];

// 16B no-return global float reduction (PTX 8.1+, sm_90+)
__device__ __forceinline__ void red_add_v4(float4* addr, float4 v) {
    asm volatile("red.global.add.v4.f32 [%0], {%1,%2,%3,%4};"
                 :: "l"(addr), "f"(v.x), "f"(v.y), "f"(v.z), "f"(v.w)
                 : "memory");
}

// ---------------- kernels ----------------

__global__ void k_zero() {
    size_t i = (size_t)blockIdx.x * blockDim.x + threadIdx.x;
    size_t stride = (size_t)gridDim.x * blockDim.x;
    const float4 z = make_float4(0.f, 0.f, 0.f, 0.f);
    const size_t n1 = (size_t)NN * NB * HIDD / 4;
    for (size_t j = i; j < n1; j += stride) ((float4*)g_agg1)[j] = z;
    const size_t n2 = (size_t)NN * NB * OUTD / 4;
    for (size_t j = i; j < n2; j += stride) ((float4*)g_agg2)[j] = z;
    for (size_t j = i; j < NN; j += stride) { g_odeg[j] = 0; g_ideg[j] = 0; }
}

__global__ void k_deg(const int* __restrict__ src, const int* __restrict__ dst) {
    int i = blockIdx.x * blockDim.x + threadIdx.x;
    int stride = gridDim.x * blockDim.x;
    for (int e = i; e < NE; e += stride) {
        atomicAdd(&g_odeg[__ldg(src + e)], 1);
        atomicAdd(&g_ideg[__ldg(dst + e)], 1);
    }
}

__global__ void k_norm() {
    int i = blockIdx.x * blockDim.x + threadIdx.x;
    if (i < NN) {
        g_snorm[i] = rsqrtf((float)max(g_odeg[i], 1));
        g_dnorm[i] = rsqrtf((float)max(g_ideg[i], 1));
    }
}

// z1[n][b*64+f] = s_norm[n] * sum_k h[b][n][k] * W1[k][f]
__global__ void __launch_bounds__(256) k_gemm1(const float* __restrict__ h,
                                               const float* __restrict__ W1) {
    __shared__ float sW[IND * HIDD];
    int tid = threadIdx.x;
    for (int i = tid; i < IND * HIDD; i += 256) sW[i] = W1[i];
    __syncthreads();

    int row = blockIdx.x * 256 + tid;
    if (row >= NN * NB) return;
    int n = row % NN;
    int b = row / NN;
    const float* hrow = h + ((size_t)b * NN + n) * IND;

    float acc[HIDD];
    #pragma unroll
    for (int f = 0; f < HIDD; f++) acc[f] = 0.f;

    #pragma unroll 4
    for (int k = 0; k < IND; k++) {
        float hv = __ldg(hrow + k);
        #pragma unroll
        for (int f = 0; f < HIDD; f++) acc[f] += hv * sW[k * HIDD + f];
    }

    float s = g_snorm[n];
    float* zp = g_z1 + ((size_t)n * NB + b) * HIDD;
    #pragma unroll
    for (int f = 0; f < HIDD; f += 4) {
        float4 v = make_float4(s * acc[f], s * acc[f + 1], s * acc[f + 2], s * acc[f + 3]);
        *(float4*)(zp + f) = v;
    }
}

// agg1[dst] += z1[src]   (256 floats per edge, warp-per-edge, 2x v4-red per lane)
__global__ void k_scat1(const int* __restrict__ src, const int* __restrict__ dst) {
    int lane = threadIdx.x & 31;
    int warp = (blockIdx.x * blockDim.x + threadIdx.x) >> 5;
    int nwarp = (gridDim.x * blockDim.x) >> 5;
    for (int e = warp; e < NE; e += nwarp) {
        int s = __ldg(src + e);
        int d = __ldg(dst + e);
        const float4* zp = (const float4*)(g_z1 + (size_t)s * (NB * HIDD));
        float4* ap = (float4*)(g_agg1 + (size_t)d * (NB * HIDD));
        float4 v0 = zp[lane];
        float4 v1 = zp[lane + 32];
        red_add_v4(ap + lane, v0);
        red_add_v4(ap + lane + 32, v1);
    }
}

// z2[n][b*32+f] = s_norm[n] * sum_k relu(agg1[n][b*64+k]*d_norm[n] + b1[k]) * W2[k][f]
__global__ void __launch_bounds__(256) k_gemm2(const float* __restrict__ W2,
                                               const float* __restrict__ b1) {
    __shared__ float sW[HIDD * OUTD];
    __shared__ float sb[HIDD];
    int tid = threadIdx.x;
    for (int i = tid; i < HIDD * OUTD; i += 256) sW[i] = W2[i];
    if (tid < HIDD) sb[tid] = b1[tid];
    __syncthreads();

    int row = blockIdx.x * 256 + tid;
    if (row >= NN * NB) return;
    int n = row % NN;
    int b = row / NN;
    const float* arow = g_agg1 + ((size_t)n * NB + b) * HIDD;
    float dn = g_dnorm[n];

    float acc[OUTD];
    #pragma unroll
    for (int f = 0; f < OUTD; f++) acc[f] = 0.f;

    #pragma unroll 4
    for (int k = 0; k < HIDD; k++) {
        float y = fmaxf(arow[k] * dn + sb[k], 0.f);
        #pragma unroll
        for (int f = 0; f < OUTD; f++) acc[f] += y * sW[k * OUTD + f];
    }

    float s = g_snorm[n];
    float* zp = g_z2 + ((size_t)n * NB + b) * OUTD;
    #pragma unroll
    for (int f = 0; f < OUTD; f += 4) {
        float4 v = make_float4(s * acc[f], s * acc[f + 1], s * acc[f + 2], s * acc[f + 3]);
        *(float4*)(zp + f) = v;
    }
}

// agg2[dst] += z2[src]   (128 floats per edge, warp-per-edge, 1x v4-red per lane)
__global__ void k_scat2(const int* __restrict__ src, const int* __restrict__ dst) {
    int lane = threadIdx.x & 31;
    int warp = (blockIdx.x * blockDim.x + threadIdx.x) >> 5;
    int nwarp = (gridDim.x * blockDim.x) >> 5;
    for (int e = warp; e < NE; e += nwarp) {
        int s = __ldg(src + e);
        int d = __ldg(dst + e);
        const float4* zp = (const float4*)(g_z2 + (size_t)s * (NB * OUTD));
        float4* ap = (float4*)(g_agg2 + (size_t)d * (NB * OUTD));
        float4 v = zp[lane];
        red_add_v4(ap + lane, v);
    }
}

// out[b][n][f] = agg2[n][b*32+f] * d_norm[n] + b2[f]
__global__ void k_out(const float* __restrict__ b2, float* __restrict__ out) {
    size_t i = (size_t)blockIdx.x * blockDim.x + threadIdx.x;  // float4 index
    const size_t total4 = (size_t)NN * NB * OUTD / 4;
    if (i >= total4) return;
    size_t j = i * 4;
    int f = (int)(j % OUTD);
    int b = (int)((j / OUTD) % NB);
    int n = (int)(j / (OUTD * NB));
    float4 v = ((const float4*)g_agg2)[i];
    float dn = g_dnorm[n];
    float4 bb = *(const float4*)(b2 + f);
    v.x = v.x * dn + bb.x;
    v.y = v.y * dn + bb.y;
    v.z = v.z * dn + bb.z;
    v.w = v.w * dn + bb.w;
    *(float4*)(out + ((size_t)b * NN + n) * OUTD + f) = v;
}

// ---------------- launch ----------------

extern "C" void kernel_launch(void* const* d_in, const int* in_sizes, int n_in,
                              void* d_out, int out_size) {
    const float* h  = (const float*)d_in[0];
    const float* W1 = (const float*)d_in[1];
    const float* b1 = (const float*)d_in[2];
    const float* W2 = (const float*)d_in[3];
    const float* b2 = (const float*)d_in[4];
    const int* src  = (const int*)d_in[5];
    const int* dst  = (const int*)d_in[6];
    float* out = (float*)d_out;

    k_zero<<<4096, 256>>>();
    k_deg<<<2048, 256>>>(src, dst);
    k_norm<<<(NN + 255) / 256, 256>>>();
    k_gemm1<<<(NN * NB + 255) / 256, 256>>>(h, W1);
    k_scat1<<<4096, 256>>>(src, dst);
    k_gemm2<<<(NN * NB + 255) / 256, 256>>>(W2, b1);
    k_scat2<<<4096, 256>>>(src, dst);
    k_out<<<((NN * NB * OUTD / 4) + 255) / 256, 256>>>(b2, out);
}

// round 2
// speedup vs baseline: 2.2968x; 2.2968x over previous
#include <cuda_runtime.h>
#include <cuda_bf16.h>

#define NN   50000
#define NE   800000
#define NB   4
#define IND  64
#define HIDD 64
#define OUTD 32
#define NROWS (NN * NB)          // 200000

typedef unsigned long long u64;

// ---------------- scratch (static device globals) ----------------
__device__ __align__(16) float g_z1  [(size_t)NN * NB * HIDD]; // (h@W1)*snorm, node-major
__device__ __align__(16) float g_agg1[(size_t)NN * NB * HIDD]; // gather target layer 1
__device__ __align__(16) float g_z2  [(size_t)NN * NB * OUTD]; // (relu@W2)*snorm, node-major
__device__ float g_snorm[NN];
__device__ float g_dnorm[NN];
__device__ int   g_odeg[NN];
__device__ int   g_ideg[NN];
__device__ int   g_incl[NN];      // per-block inclusive scan of ideg
__device__ int   g_bsum[128];     // block sums
__device__ int   g_boff[128];     // exclusive block offsets
__device__ int   g_coff[NN];      // CSR offsets (exclusive, by dst)
__device__ int   g_cur [NN];      // fill cursors
__device__ int   g_esrc[NE];      // edge src ids grouped by dst

// ---------------- f32x2 packed-FMA helpers (Blackwell FFMA2) ----------------
__device__ __forceinline__ u64 pack2(float x, float y) {
    u64 r; asm("mov.b64 %0, {%1,%2};" : "=l"(r) : "f"(x), "f"(y)); return r;
}
__device__ __forceinline__ void ffma2(u64& d, u64 a, u64 b) {
    asm("fma.rn.f32x2 %0, %1, %2, %0;" : "+l"(d) : "l"(a), "l"(b));
}
__device__ __forceinline__ float2 unpack2(u64 v) {
    float2 f; asm("mov.b64 {%0,%1}, %2;" : "=f"(f.x), "=f"(f.y) : "l"(v)); return f;
}

// ---------------- small prep kernels ----------------

__global__ void k_zero_deg() {
    int i = blockIdx.x * blockDim.x + threadIdx.x;
    if (i < NN) { g_odeg[i] = 0; g_ideg[i] = 0; }
}

__global__ void k_deg(const int* __restrict__ src, const int* __restrict__ dst) {
    int i = blockIdx.x * blockDim.x + threadIdx.x;
    int stride = gridDim.x * blockDim.x;
    for (int e = i; e < NE; e += stride) {
        atomicAdd(&g_odeg[__ldg(src + e)], 1);
        atomicAdd(&g_ideg[__ldg(dst + e)], 1);
    }
}

__global__ void k_norm() {
    int i = blockIdx.x * blockDim.x + threadIdx.x;
    if (i < NN) {
        g_snorm[i] = rsqrtf((float)max(g_odeg[i], 1));
        g_dnorm[i] = rsqrtf((float)max(g_ideg[i], 1));
    }
}

// --- 3-kernel exclusive scan of ideg -> g_coff, g_cur ---
#define SCAN_BLK 512
#define N_SCAN_BLKS ((NN + SCAN_BLK - 1) / SCAN_BLK)   // 98

__global__ void k_scan1() {
    __shared__ int sh[SCAN_BLK];
    int t = threadIdx.x, g = blockIdx.x * SCAN_BLK + t;
    int v = (g < NN) ? g_ideg[g] : 0;
    sh[t] = v; __syncthreads();
    for (int o = 1; o < SCAN_BLK; o <<= 1) {
        int x = (t >= o) ? sh[t - o] : 0;
        __syncthreads();
        sh[t] += x;
        __syncthreads();
    }
    if (g < NN) g_incl[g] = sh[t];
    if (t == SCAN_BLK - 1) g_bsum[blockIdx.x] = sh[t];
}

__global__ void k_scan2() {   // 1 block, 128 threads (N_SCAN_BLKS=98 <= 128)
    __shared__ int sh[128];
    int t = threadIdx.x;
    int v = (t < N_SCAN_BLKS) ? g_bsum[t] : 0;
    sh[t] = v; __syncthreads();
    for (int o = 1; o < 128; o <<= 1) {
        int x = (t >= o) ? sh[t - o] : 0;
        __syncthreads();
        sh[t] += x;
        __syncthreads();
    }
    if (t < N_SCAN_BLKS) g_boff[t] = sh[t] - v;   // exclusive
}

__global__ void k_scan3() {
    int g = blockIdx.x * blockDim.x + threadIdx.x;
    if (g < NN) {
        int ex = g_incl[g] - g_ideg[g] + g_boff[g / SCAN_BLK];
        g_coff[g] = ex;
        g_cur[g] = ex;
    }
}

__global__ void k_fill(const int* __restrict__ src, const int* __restrict__ dst) {
    int i = blockIdx.x * blockDim.x + threadIdx.x;
    int stride = gridDim.x * blockDim.x;
    for (int e = i; e < NE; e += stride) {
        int d = __ldg(dst + e);
        int pos = atomicAdd(&g_cur[d], 1);
        g_esrc[pos] = __ldg(src + e);
    }
}

// ---------------- GEMM 1: z1[q=n*4+b] = snorm[n] * (h[r=b*NN+n] @ W1) ----------------
// block: 128 rows x 64 cols, 256 threads; thread: rows {lane+32i}, cols cgrp*8..+7
__global__ void __launch_bounds__(256) k_gemm1(const float* __restrict__ h,
                                               const float* __restrict__ W1) {
    __shared__ float sA[IND][128];   // transposed + XOR-swizzled: sA[k][r ^ ((k>>2)&15)]
    __shared__ float sB[IND * HIDD]; // W1 natural [k][f]
    int tid = threadIdx.x;
    int lane = tid & 31;
    int cgrp = tid >> 5;             // 0..7
    int c0 = cgrp * 8;
    int row0 = blockIdx.x * 128;

    // fill W1
    #pragma unroll
    for (int i = tid; i < IND * HIDD; i += 256) sB[i] = __ldg(W1 + i);
    // fill A (transposed, swizzled)
    #pragma unroll
    for (int it = 0; it < 8; it++) {
        int idx = tid + it * 256;        // 0..2047
        int r_l = idx >> 4;              // 0..127
        int kq  = idx & 15;              // float4 index in k
        int row = row0 + r_l;
        float4 v = make_float4(0.f, 0.f, 0.f, 0.f);
        if (row < NROWS) v = __ldg((const float4*)(h + (size_t)row * IND + kq * 4));
        int col = r_l ^ kq;              // swizzle: (k>>2)&15 == kq
        sA[kq * 4 + 0][col] = v.x;
        sA[kq * 4 + 1][col] = v.y;
        sA[kq * 4 + 2][col] = v.z;
        sA[kq * 4 + 3][col] = v.w;
    }
    __syncthreads();

    u64 acc[4][4];
    #pragma unroll
    for (int r = 0; r < 4; r++)
        #pragma unroll
        for (int c = 0; c < 4; c++) acc[r][c] = 0ull;

    #pragma unroll 4
    for (int k = 0; k < IND; k++) {
        int s = (k >> 2) & 15;
        u64 ap[4];
        #pragma unroll
        for (int r = 0; r < 4; r++) {
            float a = sA[k][(lane + 32 * r) ^ s];
            ap[r] = pack2(a, a);
        }
        ulonglong2 b01 = *(const ulonglong2*)&sB[k * HIDD + c0];
        ulonglong2 b23 = *(const ulonglong2*)&sB[k * HIDD + c0 + 4];
        u64 bp[4] = {b01.x, b01.y, b23.x, b23.y};
        #pragma unroll
        for (int r = 0; r < 4; r++)
            #pragma unroll
            for (int c = 0; c < 4; c++) ffma2(acc[r][c], ap[r], bp[c]);
    }

    #pragma unroll
    for (int r = 0; r < 4; r++) {
        int row = row0 + lane + 32 * r;
        if (row >= NROWS) continue;
        int b = row / NN, n = row - b * NN;
        float sc = g_snorm[n];
        int q = n * NB + b;
        float* zp = g_z1 + (size_t)q * HIDD + c0;
        float2 p0 = unpack2(acc[r][0]), p1 = unpack2(acc[r][1]);
        float2 p2 = unpack2(acc[r][2]), p3 = unpack2(acc[r][3]);
        *(float4*)(zp)     = make_float4(sc * p0.x, sc * p0.y, sc * p1.x, sc * p1.y);
        *(float4*)(zp + 4) = make_float4(sc * p2.x, sc * p2.y, sc * p3.x, sc * p3.y);
    }
}

// ---------------- gather layer 1: agg1[n] = sum_{e: dst=n} z1[src[e]] ----------------
// warp per node; 256-float rows -> 2 float4 per lane
__global__ void __launch_bounds__(256) k_agg1() {
    int lane = threadIdx.x & 31;
    int n = blockIdx.x * 8 + (threadIdx.x >> 5);
    if (n >= NN) return;
    int beg = g_coff[n];
    int deg = g_ideg[n];
    float4 a0 = make_float4(0.f, 0.f, 0.f, 0.f);
    float4 a1 = a0;
    for (int i = 0; i < deg; i++) {
        int s = __ldg(g_esrc + beg + i);
        const float4* zp = (const float4*)(g_z1 + (size_t)s * (NB * HIDD));
        float4 v0 = __ldg(zp + lane);
        float4 v1 = __ldg(zp + lane + 32);
        a0.x += v0.x; a0.y += v0.y; a0.z += v0.z; a0.w += v0.w;
        a1.x += v1.x; a1.y += v1.y; a1.z += v1.z; a1.w += v1.w;
    }
    float4* ap = (float4*)(g_agg1 + (size_t)n * (NB * HIDD));
    ap[lane] = a0;
    ap[lane + 32] = a1;
}

// ---------------- GEMM 2: z2[q] = snorm[n] * (relu(agg1[q]*dnorm[n] + b1) @ W2) ----------------
// block: 128 rows x 32 cols, 256 threads; thread: rows {lane+32i}, cols cgrp*4..+3
__global__ void __launch_bounds__(256) k_gemm2(const float* __restrict__ W2,
                                               const float* __restrict__ b1) {
    __shared__ float sA[HIDD][128];
    __shared__ float sB[HIDD * OUTD];
    int tid = threadIdx.x;
    int lane = tid & 31;
    int cgrp = tid >> 5;
    int c0 = cgrp * 4;
    int row0 = blockIdx.x * 128;

    #pragma unroll
    for (int i = tid; i < HIDD * OUTD; i += 256) sB[i] = __ldg(W2 + i);
    #pragma unroll
    for (int it = 0; it < 8; it++) {
        int idx = tid + it * 256;
        int r_l = idx >> 4;
        int kq  = idx & 15;
        int row = row0 + r_l;
        float4 v = make_float4(0.f, 0.f, 0.f, 0.f);
        if (row < NROWS) {
            float dn = g_dnorm[row >> 2];  // q = n*4+b -> n = q/4
            float4 a = *(const float4*)(g_agg1 + (size_t)row * HIDD + kq * 4);
            const float4 bb = __ldg((const float4*)(b1 + kq * 4));
            v.x = fmaxf(a.x * dn + bb.x, 0.f);
            v.y = fmaxf(a.y * dn + bb.y, 0.f);
            v.z = fmaxf(a.z * dn + bb.z, 0.f);
            v.w = fmaxf(a.w * dn + bb.w, 0.f);
        }
        int col = r_l ^ kq;
        sA[kq * 4 + 0][col] = v.x;
        sA[kq * 4 + 1][col] = v.y;
        sA[kq * 4 + 2][col] = v.z;
        sA[kq * 4 + 3][col] = v.w;
    }
    __syncthreads();

    u64 acc[4][2];
    #pragma unroll
    for (int r = 0; r < 4; r++) { acc[r][0] = 0ull; acc[r][1] = 0ull; }

    #pragma unroll 4
    for (int k = 0; k < HIDD; k++) {
        int s = (k >> 2) & 15;
        u64 ap[4];
        #pragma unroll
        for (int r = 0; r < 4; r++) {
            float a = sA[k][(lane + 32 * r) ^ s];
            ap[r] = pack2(a, a);
        }
        ulonglong2 b01 = *(const ulonglong2*)&sB[k * OUTD + c0];
        #pragma unroll
        for (int r = 0; r < 4; r++) {
            ffma2(acc[r][0], ap[r], b01.x);
            ffma2(acc[r][1], ap[r], b01.y);
        }
    }

    #pragma unroll
    for (int r = 0; r < 4; r++) {
        int row = row0 + lane + 32 * r;
        if (row >= NROWS) continue;
        float sc = g_snorm[row >> 2];
        float* zp = g_z2 + (size_t)row * OUTD + c0;
        float2 p0 = unpack2(acc[r][0]), p1 = unpack2(acc[r][1]);
        *(float4*)zp = make_float4(sc * p0.x, sc * p0.y, sc * p1.x, sc * p1.y);
    }
}

// ---------------- gather layer 2 + fused epilogue -> out[b][n][f] ----------------
// warp per node; 128-float node block -> 1 float4 per lane; lane -> (b = lane>>3, fq = lane&7)
__global__ void __launch_bounds__(256) k_agg2(const float* __restrict__ b2,
                                              float* __restrict__ out) {
    int lane = threadIdx.x & 31;
    int n = blockIdx.x * 8 + (threadIdx.x >> 5);
    if (n >= NN) return;
    int beg = g_coff[n];
    int deg = g_ideg[n];
    float4 a = make_float4(0.f, 0.f, 0.f, 0.f);
    for (int i = 0; i < deg; i++) {
        int s = __ldg(g_esrc + beg + i);
        float4 v = __ldg((const float4*)(g_z2 + (size_t)s * (NB * OUTD)) + lane);
        a.x += v.x; a.y += v.y; a.z += v.z; a.w += v.w;
    }
    float dn = g_dnorm[n];
    int b = lane >> 3, fq = lane & 7;
    float4 bb = __ldg((const float4*)(b2 + fq * 4));
    float4 o = make_float4(a.x * dn + bb.x, a.y * dn + bb.y,
                           a.z * dn + bb.z, a.w * dn + bb.w);
    *(float4*)(out + ((size_t)b * NN + n) * OUTD + fq * 4) = o;
}

// ---------------- launch ----------------

extern "C" void kernel_launch(void* const* d_in, const int* in_sizes, int n_in,
                              void* d_out, int out_size) {
    const float* h  = (const float*)d_in[0];
    const float* W1 = (const float*)d_in[1];
    const float* b1 = (const float*)d_in[2];
    const float* W2 = (const float*)d_in[3];
    const float* b2 = (const float*)d_in[4];
    const int* src  = (const int*)d_in[5];
    const int* dst  = (const int*)d_in[6];
    float* out = (float*)d_out;

    k_zero_deg<<<(NN + 255) / 256, 256>>>();
    k_deg<<<2048, 256>>>(src, dst);
    k_norm<<<(NN + 255) / 256, 256>>>();
    k_scan1<<<N_SCAN_BLKS, SCAN_BLK>>>();
    k_scan2<<<1, 128>>>();
    k_scan3<<<(NN + 255) / 256, 256>>>();
    k_fill<<<2048, 256>>>(src, dst);
    k_gemm1<<<(NROWS + 127) / 128, 256>>>(h, W1);
    k_agg1<<<(NN + 7) / 8, 256>>>();
    k_gemm2<<<(NROWS + 127) / 128, 256>>>(W2, b1);
    k_agg2<<<(NN + 7) / 8, 256>>>(b2, out);
}

// round 4
// speedup vs baseline: 2.8362x; 1.2348x over previous
#include <cuda_runtime.h>
#include <cuda_fp16.h>

#define NN   50000
#define NE   800000
#define NB   4
#define IND  64
#define HIDD 64
#define OUTD 32
#define NROWS (NN * NB)          // 200000

typedef unsigned long long u64;

// ---------------- scratch (static device globals) ----------------
__device__ __align__(16) __half g_z1[(size_t)NN * NB * HIDD];  // fp16 (h@W1)*snorm, node-major [q=n*4+b][64]
__device__ __align__(16) float  g_agg1[(size_t)NN * NB * HIDD];
__device__ __align__(16) __half g_z2[(size_t)NN * NB * OUTD];  // fp16 (relu@W2)*snorm
__device__ float g_snorm[NN];
__device__ float g_dnorm[NN];
__device__ int   g_odeg[NN];
__device__ int   g_ideg[NN];
__device__ int   g_incl[NN];
__device__ int   g_bsum[128];
__device__ int   g_boff[128];
__device__ int   g_coff[NN];
__device__ int   g_cur [NN];
__device__ int   g_esrc[NE];

// ---------------- f32x2 packed-FMA helpers (Blackwell FFMA2) ----------------
__device__ __forceinline__ u64 pack2(float x, float y) {
    u64 r; asm("mov.b64 %0, {%1,%2};" : "=l"(r) : "f"(x), "f"(y)); return r;
}
__device__ __forceinline__ void ffma2(u64& d, u64 a, u64 b) {
    asm("fma.rn.f32x2 %0, %1, %2, %0;" : "+l"(d) : "l"(a), "l"(b));
}
__device__ __forceinline__ float2 unpack2(u64 v) {
    float2 f; asm("mov.b64 {%0,%1}, %2;" : "=f"(f.x), "=f"(f.y) : "l"(v)); return f;
}

// ---------------- small prep kernels ----------------

__global__ void k_zero_deg() {
    int i = blockIdx.x * blockDim.x + threadIdx.x;
    if (i < NN) { g_odeg[i] = 0; g_ideg[i] = 0; }
}

__global__ void k_deg(const int* __restrict__ src, const int* __restrict__ dst) {
    int i = blockIdx.x * blockDim.x + threadIdx.x;
    int stride = gridDim.x * blockDim.x;
    for (int e = i; e < NE; e += stride) {
        atomicAdd(&g_odeg[__ldg(src + e)], 1);
        atomicAdd(&g_ideg[__ldg(dst + e)], 1);
    }
}

__global__ void k_norm() {
    int i = blockIdx.x * blockDim.x + threadIdx.x;
    if (i < NN) {
        g_snorm[i] = rsqrtf((float)max(g_odeg[i], 1));
        g_dnorm[i] = rsqrtf((float)max(g_ideg[i], 1));
    }
}

#define SCAN_BLK 512
#define N_SCAN_BLKS ((NN + SCAN_BLK - 1) / SCAN_BLK)   // 98

__global__ void k_scan1() {
    __shared__ int sh[SCAN_BLK];
    int t = threadIdx.x, g = blockIdx.x * SCAN_BLK + t;
    int v = (g < NN) ? g_ideg[g] : 0;
    sh[t] = v; __syncthreads();
    for (int o = 1; o < SCAN_BLK; o <<= 1) {
        int x = (t >= o) ? sh[t - o] : 0;
        __syncthreads();
        sh[t] += x;
        __syncthreads();
    }
    if (g < NN) g_incl[g] = sh[t];
    if (t == SCAN_BLK - 1) g_bsum[blockIdx.x] = sh[t];
}

__global__ void k_scan2() {
    __shared__ int sh[128];
    int t = threadIdx.x;
    int v = (t < N_SCAN_BLKS) ? g_bsum[t] : 0;
    sh[t] = v; __syncthreads();
    for (int o = 1; o < 128; o <<= 1) {
        int x = (t >= o) ? sh[t - o] : 0;
        __syncthreads();
        sh[t] += x;
        __syncthreads();
    }
    if (t < N_SCAN_BLKS) g_boff[t] = sh[t] - v;
}

__global__ void k_scan3() {
    int g = blockIdx.x * blockDim.x + threadIdx.x;
    if (g < NN) {
        int ex = g_incl[g] - g_ideg[g] + g_boff[g / SCAN_BLK];
        g_coff[g] = ex;
        g_cur[g] = ex;
    }
}

__global__ void k_fill(const int* __restrict__ src, const int* __restrict__ dst) {
    int i = blockIdx.x * blockDim.x + threadIdx.x;
    int stride = gridDim.x * blockDim.x;
    for (int e = i; e < NE; e += stride) {
        int d = __ldg(dst + e);
        int pos = atomicAdd(&g_cur[d], 1);
        g_esrc[pos] = __ldg(src + e);
    }
}

// ---------------- GEMM 1: z1[q=n*4+b] = half( snorm[n] * (h[r=b*NN+n] @ W1) ) ----------------
__global__ void __launch_bounds__(256) k_gemm1(const float* __restrict__ h,
                                               const float* __restrict__ W1) {
    __shared__ float sA[IND][128];   // transposed + XOR-swizzled
    __shared__ float sB[IND * HIDD];
    int tid = threadIdx.x;
    int lane = tid & 31;
    int cgrp = tid >> 5;
    int c0 = cgrp * 8;
    int row0 = blockIdx.x * 128;

    #pragma unroll
    for (int i = tid; i < IND * HIDD; i += 256) sB[i] = __ldg(W1 + i);
    #pragma unroll
    for (int it = 0; it < 8; it++) {
        int idx = tid + it * 256;
        int r_l = idx >> 4;
        int kq  = idx & 15;
        int row = row0 + r_l;
        float4 v = make_float4(0.f, 0.f, 0.f, 0.f);
        if (row < NROWS) v = __ldg((const float4*)(h + (size_t)row * IND + kq * 4));
        int col = r_l ^ kq;
        sA[kq * 4 + 0][col] = v.x;
        sA[kq * 4 + 1][col] = v.y;
        sA[kq * 4 + 2][col] = v.z;
        sA[kq * 4 + 3][col] = v.w;
    }
    __syncthreads();

    u64 acc[4][4];
    #pragma unroll
    for (int r = 0; r < 4; r++)
        #pragma unroll
        for (int c = 0; c < 4; c++) acc[r][c] = 0ull;

    #pragma unroll 4
    for (int k = 0; k < IND; k++) {
        int s = (k >> 2) & 15;
        u64 ap[4];
        #pragma unroll
        for (int r = 0; r < 4; r++) {
            float a = sA[k][(lane + 32 * r) ^ s];
            ap[r] = pack2(a, a);
        }
        ulonglong2 b01 = *(const ulonglong2*)&sB[k * HIDD + c0];
        ulonglong2 b23 = *(const ulonglong2*)&sB[k * HIDD + c0 + 4];
        u64 bp[4] = {b01.x, b01.y, b23.x, b23.y};
        #pragma unroll
        for (int r = 0; r < 4; r++)
            #pragma unroll
            for (int c = 0; c < 4; c++) ffma2(acc[r][c], ap[r], bp[c]);
    }

    #pragma unroll
    for (int r = 0; r < 4; r++) {
        int row = row0 + lane + 32 * r;
        if (row >= NROWS) continue;
        int b = row / NN, n = row - b * NN;
        float sc = g_snorm[n];
        int q = n * NB + b;
        float2 p0 = unpack2(acc[r][0]), p1 = unpack2(acc[r][1]);
        float2 p2 = unpack2(acc[r][2]), p3 = unpack2(acc[r][3]);
        __half2 h0 = __floats2half2_rn(sc * p0.x, sc * p0.y);
        __half2 h1 = __floats2half2_rn(sc * p1.x, sc * p1.y);
        __half2 h2 = __floats2half2_rn(sc * p2.x, sc * p2.y);
        __half2 h3 = __floats2half2_rn(sc * p3.x, sc * p3.y);
        uint4 st;
        st.x = *(unsigned*)&h0; st.y = *(unsigned*)&h1;
        st.z = *(unsigned*)&h2; st.w = *(unsigned*)&h3;
        *(uint4*)(g_z1 + (size_t)q * HIDD + c0) = st;   // 16B aligned (c0 % 8 == 0)
    }
}

// ---------------- gather layer 1: agg1[n] = sum z1[src]  (fp16 in, fp32 acc/out) ----------------
// warp per node; node row = 256 halves = 512B -> per lane one 16B load (8 halves)
__global__ void __launch_bounds__(256) k_agg1() {
    int lane = threadIdx.x & 31;
    int n = blockIdx.x * 8 + (threadIdx.x >> 5);
    if (n >= NN) return;
    int beg = g_coff[n];
    int deg = g_ideg[n];
    float2 a[4];
    #pragma unroll
    for (int j = 0; j < 4; j++) a[j] = make_float2(0.f, 0.f);

    int i = 0;
    for (; i + 1 < deg; i += 2) {
        int s0 = __ldg(g_esrc + beg + i);
        int s1 = __ldg(g_esrc + beg + i + 1);
        uint4 v0 = __ldg((const uint4*)(g_z1 + (size_t)s0 * (NB * HIDD)) + lane);
        uint4 v1 = __ldg((const uint4*)(g_z1 + (size_t)s1 * (NB * HIDD)) + lane);
        const unsigned* w0 = &v0.x;
        const unsigned* w1 = &v1.x;
        #pragma unroll
        for (int j = 0; j < 4; j++) {
            float2 f0 = __half22float2(*(const __half2*)&w0[j]);
            float2 f1 = __half22float2(*(const __half2*)&w1[j]);
            a[j].x += f0.x + f1.x;
            a[j].y += f0.y + f1.y;
        }
    }
    if (i < deg) {
        int s0 = __ldg(g_esrc + beg + i);
        uint4 v0 = __ldg((const uint4*)(g_z1 + (size_t)s0 * (NB * HIDD)) + lane);
        const unsigned* w0 = &v0.x;
        #pragma unroll
        for (int j = 0; j < 4; j++) {
            float2 f0 = __half22float2(*(const __half2*)&w0[j]);
            a[j].x += f0.x;
            a[j].y += f0.y;
        }
    }
    float* ap = g_agg1 + (size_t)n * (NB * HIDD) + lane * 8;
    *(float4*)(ap)     = make_float4(a[0].x, a[0].y, a[1].x, a[1].y);
    *(float4*)(ap + 4) = make_float4(a[2].x, a[2].y, a[3].x, a[3].y);
}

// ---------------- GEMM 2: z2[q] = half( snorm * (relu(agg1*dnorm + b1) @ W2) ) ----------------
__global__ void __launch_bounds__(256) k_gemm2(const float* __restrict__ W2,
                                               const float* __restrict__ b1) {
    __shared__ float sA[HIDD][128];
    __shared__ float sB[HIDD * OUTD];
    int tid = threadIdx.x;
    int lane = tid & 31;
    int cgrp = tid >> 5;
    int c0 = cgrp * 4;
    int row0 = blockIdx.x * 128;

    #pragma unroll
    for (int i = tid; i < HIDD * OUTD; i += 256) sB[i] = __ldg(W2 + i);
    #pragma unroll
    for (int it = 0; it < 8; it++) {
        int idx = tid + it * 256;
        int r_l = idx >> 4;
        int kq  = idx & 15;
        int row = row0 + r_l;
        float4 v = make_float4(0.f, 0.f, 0.f, 0.f);
        if (row < NROWS) {
            float dn = g_dnorm[row >> 2];
            float4 a = *(const float4*)(g_agg1 + (size_t)row * HIDD + kq * 4);
            const float4 bb = __ldg((const float4*)(b1 + kq * 4));
            v.x = fmaxf(a.x * dn + bb.x, 0.f);
            v.y = fmaxf(a.y * dn + bb.y, 0.f);
            v.z = fmaxf(a.z * dn + bb.z, 0.f);
            v.w = fmaxf(a.w * dn + bb.w, 0.f);
        }
        int col = r_l ^ kq;
        sA[kq * 4 + 0][col] = v.x;
        sA[kq * 4 + 1][col] = v.y;
        sA[kq * 4 + 2][col] = v.z;
        sA[kq * 4 + 3][col] = v.w;
    }
    __syncthreads();

    u64 acc[4][2];
    #pragma unroll
    for (int r = 0; r < 4; r++) { acc[r][0] = 0ull; acc[r][1] = 0ull; }

    #pragma unroll 4
    for (int k = 0; k < HIDD; k++) {
        int s = (k >> 2) & 15;
        u64 ap[4];
        #pragma unroll
        for (int r = 0; r < 4; r++) {
            float a = sA[k][(lane + 32 * r) ^ s];
            ap[r] = pack2(a, a);
        }
        ulonglong2 b01 = *(const ulonglong2*)&sB[k * OUTD + c0];
        #pragma unroll
        for (int r = 0; r < 4; r++) {
            ffma2(acc[r][0], ap[r], b01.x);
            ffma2(acc[r][1], ap[r], b01.y);
        }
    }

    #pragma unroll
    for (int r = 0; r < 4; r++) {
        int row = row0 + lane + 32 * r;
        if (row >= NROWS) continue;
        float sc = g_snorm[row >> 2];
        float2 p0 = unpack2(acc[r][0]), p1 = unpack2(acc[r][1]);
        __half2 h0 = __floats2half2_rn(sc * p0.x, sc * p0.y);
        __half2 h1 = __floats2half2_rn(sc * p1.x, sc * p1.y);
        uint2 st;
        st.x = *(unsigned*)&h0; st.y = *(unsigned*)&h1;
        *(uint2*)(g_z2 + (size_t)row * OUTD + c0) = st;   // 8B aligned (c0 % 4 == 0)
    }
}

// ---------------- gather layer 2 + fused epilogue -> out[b][n][f] ----------------
// warp per node; node row = 128 halves = 256B -> per lane one 8B load (4 halves)
__global__ void __launch_bounds__(256) k_agg2(const float* __restrict__ b2,
                                              float* __restrict__ out) {
    int lane = threadIdx.x & 31;
    int n = blockIdx.x * 8 + (threadIdx.x >> 5);
    if (n >= NN) return;
    int beg = g_coff[n];
    int deg = g_ideg[n];
    float2 a0 = make_float2(0.f, 0.f), a1 = a0;

    int i = 0;
    for (; i + 1 < deg; i += 2) {
        int s0 = __ldg(g_esrc + beg + i);
        int s1 = __ldg(g_esrc + beg + i + 1);
        uint2 v0 = __ldg((const uint2*)(g_z2 + (size_t)s0 * (NB * OUTD)) + lane);
        uint2 v1 = __ldg((const uint2*)(g_z2 + (size_t)s1 * (NB * OUTD)) + lane);
        float2 f; 
        f = __half22float2(*(const __half2*)&v0.x); a0.x += f.x; a0.y += f.y;
        f = __half22float2(*(const __half2*)&v0.y); a1.x += f.x; a1.y += f.y;
        f = __half22float2(*(const __half2*)&v1.x); a0.x += f.x; a0.y += f.y;
        f = __half22float2(*(const __half2*)&v1.y); a1.x += f.x; a1.y += f.y;
    }
    if (i < deg) {
        int s0 = __ldg(g_esrc + beg + i);
        uint2 v0 = __ldg((const uint2*)(g_z2 + (size_t)s0 * (NB * OUTD)) + lane);
        float2 f;
        f = __half22float2(*(const __half2*)&v0.x); a0.x += f.x; a0.y += f.y;
        f = __half22float2(*(const __half2*)&v0.y); a1.x += f.x; a1.y += f.y;
    }

    float dn = g_dnorm[n];
    int b = lane >> 3, fq = lane & 7;   // lane*4 halves -> col = b*32 + fq*4
    float4 bb = __ldg((const float4*)(b2 + fq * 4));
    float4 o = make_float4(a0.x * dn + bb.x, a0.y * dn + bb.y,
                           a1.x * dn + bb.z, a1.y * dn + bb.w);
    *(float4*)(out + ((size_t)b * NN + n) * OUTD + fq * 4) = o;
}

// ---------------- launch ----------------

extern "C" void kernel_launch(void* const* d_in, const int* in_sizes, int n_in,
                              void* d_out, int out_size) {
    const float* h  = (const float*)d_in[0];
    const float* W1 = (const float*)d_in[1];
    const float* b1 = (const float*)d_in[2];
    const float* W2 = (const float*)d_in[3];
    const float* b2 = (const float*)d_in[4];
    const int* src  = (const int*)d_in[5];
    const int* dst  = (const int*)d_in[6];
    float* out = (float*)d_out;

    k_zero_deg<<<(NN + 255) / 256, 256>>>();
    k_deg<<<2048, 256>>>(src, dst);
    k_norm<<<(NN + 255) / 256, 256>>>();
    k_scan1<<<N_SCAN_BLKS, SCAN_BLK>>>();
    k_scan2<<<1, 128>>>();
    k_scan3<<<(NN + 255) / 256, 256>>>();
    k_fill<<<2048, 256>>>(src, dst);
    k_gemm1<<<(NROWS + 127) / 128, 256>>>(h, W1);
    k_agg1<<<(NN + 7) / 8, 256>>>();
    k_gemm2<<<(NROWS + 127) / 128, 256>>>(W2, b1);
    k_agg2<<<(NN + 7) / 8, 256>>>(b2, out);
}